// round 16
// baseline (speedup 1.0000x reference)
#include <cuda_runtime.h>
#include <cuda_bf16.h>
#include <cuda_fp16.h>
#include <math.h>
#include <stdint.h>

// ---------------- problem constants ----------------
#define BATCH 2
#define SEQ   2048
#define DIN   2048
#define DOUT  2048
#define NH    32
#define HD    64
#define NKV   8
#define ROWS  4096          // BATCH*SEQ
#define NQKV  3072          // Q(2048) | K(512) | V(512) per row

typedef __half h16;

// ---------------- scratch (device globals; no runtime alloc) ----------------
__device__ h16 g_Qh [(size_t)ROWS * DOUT];     // rope'd, pre-scaled fp16 Q
__device__ h16 g_KVh[(size_t)ROWS * 1024];     // K(rope'd) | V fp16
__device__ h16 g_Xh [(size_t)ROWS * DIN];      // x fp16 hi
__device__ h16 g_Xl [(size_t)ROWS * DIN];      // x fp16 lo
__device__ h16 g_CTXh[(size_t)ROWS * DOUT];
__device__ h16 g_CTXl[(size_t)ROWS * DOUT];
__device__ h16 g_WTh[(size_t)NQKV * DIN];      // rows: Wq^T | Wk^T | Wv^T (fp16)
__device__ h16 g_WoTh[(size_t)DOUT * DIN];     // Wo^T (fp16)

// ---------------- helpers ----------------
__device__ __forceinline__ uint32_t smem_u32(const void* p) {
    uint32_t a;
    asm("{ .reg .u64 t; cvta.to.shared.u64 t, %1; cvt.u32.u64 %0, t; }" : "=r"(a) : "l"(p));
    return a;
}
__device__ __forceinline__ void cp16(uint32_t dst, const void* src) {
    asm volatile("cp.async.cg.shared.global [%0], [%1], 16;" :: "r"(dst), "l"(src) : "memory");
}
__device__ __forceinline__ void cp_commit() { asm volatile("cp.async.commit_group;" ::: "memory"); }
template<int N> __device__ __forceinline__ void cp_wait() {
    asm volatile("cp.async.wait_group %0;" :: "n"(N) : "memory");
}
__device__ __forceinline__ float ex2(float x) {
    float y; asm("ex2.approx.ftz.f32 %0, %1;" : "=f"(y) : "f"(x)); return y;
}
__device__ __forceinline__ void mma16816h(float* d, const uint32_t* a, const uint32_t* b) {
    asm volatile("mma.sync.aligned.m16n8k16.row.col.f32.f16.f16.f32 "
        "{%0,%1,%2,%3}, {%4,%5,%6,%7}, {%8,%9}, {%0,%1,%2,%3};"
        : "+f"(d[0]), "+f"(d[1]), "+f"(d[2]), "+f"(d[3])
        : "r"(a[0]), "r"(a[1]), "r"(a[2]), "r"(a[3]), "r"(b[0]), "r"(b[1]));
}
__device__ __forceinline__ void ldm_x4(uint32_t* r, uint32_t addr) {
    asm volatile("ldmatrix.sync.aligned.m8n8.x4.shared.b16 {%0,%1,%2,%3}, [%4];"
        : "=r"(r[0]), "=r"(r[1]), "=r"(r[2]), "=r"(r[3]) : "r"(addr));
}
__device__ __forceinline__ void ldm_x4t(uint32_t* r, uint32_t addr) {
    asm volatile("ldmatrix.sync.aligned.m8n8.x4.trans.shared.b16 {%0,%1,%2,%3}, [%4];"
        : "=r"(r[0]), "=r"(r[1]), "=r"(r[2]), "=r"(r[3]) : "r"(addr));
}
__device__ __forceinline__ void split_h(float v, h16& h, h16& l) {
    h = __float2half_rn(v);
    l = __float2half_rn(v - __half2float(h));
}
__device__ __forceinline__ uint32_t pack_h2(float lo, float hi) {
    __half2 h = __floats2half2_rn(lo, hi);
    return *(uint32_t*)&h;
}

// ---------------- split fp32 -> fp16 hi/lo ----------------
__global__ void split_f32(const float* __restrict__ in, h16* __restrict__ oh,
                          h16* __restrict__ ol, int n4) {
    int i = blockIdx.x * blockDim.x + threadIdx.x;
    if (i >= n4) return;
    float4 v = ((const float4*)in)[i];
    h16 h0, h1, h2, h3, l0, l1, l2, l3;
    split_h(v.x, h0, l0); split_h(v.y, h1, l1);
    split_h(v.z, h2, l2); split_h(v.w, h3, l3);
    ((__half2*)oh)[2 * i]     = __halves2half2(h0, h1);
    ((__half2*)oh)[2 * i + 1] = __halves2half2(h2, h3);
    ((__half2*)ol)[2 * i]     = __halves2half2(l0, l1);
    ((__half2*)ol)[2 * i + 1] = __halves2half2(l2, l3);
}

// ---------------- fused transpose (to fp16) for ALL weights -----------------
__global__ void transpose_all(const float* __restrict__ Wq, const float* __restrict__ Wk,
                              const float* __restrict__ Wv, const float* __restrict__ Wo,
                              h16* __restrict__ WTh, h16* __restrict__ WoTh) {
    __shared__ float t[32][33];
    const int bx = blockIdx.x;
    const int kb = blockIdx.y * 32;
    const float* src; h16* dh; int N, nb;
    if (bx < 64)       { src = Wq; N = 2048; nb = bx * 32;        dh = WTh; }
    else if (bx < 80)  { src = Wk; N = 512;  nb = (bx - 64) * 32; dh = WTh + (size_t)2048 * DIN; }
    else if (bx < 96)  { src = Wv; N = 512;  nb = (bx - 80) * 32; dh = WTh + (size_t)2560 * DIN; }
    else               { src = Wo; N = 2048; nb = (bx - 96) * 32; dh = WoTh; }

    int tx = threadIdx.x, ty = threadIdx.y; // 32 x 8
#pragma unroll
    for (int i = 0; i < 32; i += 8)
        t[ty + i][tx] = src[(size_t)(kb + ty + i) * N + nb + tx];
    __syncthreads();
#pragma unroll
    for (int i = 0; i < 32; i += 8)
        dh[(size_t)(nb + ty + i) * DIN + kb + tx] = __float2half_rn(t[tx][ty + i]);
}

// ---------------- fp16 2-term mma.sync GEMM: C = (Ah+Al)*Bh^T ---------------
// CTA 128x64, BK=32, 8 warps (4m x 2n, warp tile 32x32), 3 CTAs/SM.
// MODE 0: plain fp32 C output. MODE 1: fused rope + fp16 emit to Qh/KVh.
#define BM 128
#define BN 64
#define BK 32
#define NSTG 2
#define KITER (DIN / BK)
#define HS 40
#define GS_ATILE (128 * HS)                // halfs (Ah or Al tile)
#define GS_BTILE (64 * HS)                 // halfs
#define GS_STAGE (2 * GS_ATILE + GS_BTILE) // 12800 halfs = 25600 B
#define GEMM_SMEM (NSTG * GS_STAGE * 2)    // 51200 B
#define CS 0.1803368801111244f             // 0.125 / ln(2)
#define ESTR 72                            // fp32 staging stride (floats)

__device__ __forceinline__ void load_stage2(const h16* __restrict__ Ah,
                                            const h16* __restrict__ Al,
                                            const h16* __restrict__ Bh,
                                            uint32_t st, int m0, int n0, int k0, int tid) {
#pragma unroll
    for (int t = 0; t < 2; ++t) {
        int idx = t * 256 + tid;           // 0..511: 128 rows x 4 chunks (8 halfs)
        int r = idx >> 2, c = idx & 3;
        uint32_t off = (r * HS + c * 8) * 2;
        size_t ga = (size_t)(m0 + r) * DIN + k0 + c * 8;
        cp16(st + off,                 Ah + ga);
        cp16(st + GS_ATILE * 2 + off,  Al + ga);
    }
    {
        int r = tid >> 2, c = tid & 3;     // 64 rows x 4 chunks
        cp16(st + 2 * GS_ATILE * 2 + (r * HS + c * 8) * 2,
             Bh + (size_t)(n0 + r) * DIN + k0 + c * 8);
    }
    cp_commit();
}

template<int MODE>
__global__ __launch_bounds__(256, 3) void gemm_fp16x2(const h16* __restrict__ Ah,
                                                      const h16* __restrict__ Al,
                                                      const h16* __restrict__ Bh,
                                                      float* __restrict__ C, int Ntot,
                                                      const float* __restrict__ cosT,
                                                      const float* __restrict__ sinT,
                                                      h16* __restrict__ Qh,
                                                      h16* __restrict__ KVh) {
    extern __shared__ char smem_raw[];
    const uint32_t sbase = smem_u32(smem_raw);
    const int tid  = threadIdx.x;
    const int lane = tid & 31;
    const int warp = tid >> 5;
    const int wm = warp & 3;               // 4 warps in m (32 rows each)
    const int wn = warp >> 2;              // 2 warps in n (32 cols each)
    const int gid = lane >> 2;
    const int tig = lane & 3;
    const int m0 = blockIdx.y * BM;
    const int n0 = blockIdx.x * BN;

    const int arow = lane & 15;
    const int acol = (lane >> 4) * 8;
    const int brow = (lane & 7) + ((lane >> 4) << 3);
    const int bcol = ((lane >> 3) & 1) * 8;

    float acc[2][4][4];
#pragma unroll
    for (int i = 0; i < 2; ++i)
#pragma unroll
        for (int j = 0; j < 4; ++j)
#pragma unroll
            for (int r = 0; r < 4; ++r) acc[i][j][r] = 0.f;

    load_stage2(Ah, Al, Bh, sbase, m0, n0, 0, tid);
    int load_it = 1;

    for (int it = 0; it < KITER; ++it) {
        bool issued = (load_it < KITER);
        if (issued) {
            load_stage2(Ah, Al, Bh, sbase + (load_it & 1) * GS_STAGE * 2,
                        m0, n0, load_it * BK, tid);
            ++load_it;
        }
        if (issued) cp_wait<1>(); else cp_wait<0>();
        __syncthreads();

        const uint32_t st = sbase + (it & 1) * GS_STAGE * 2;

#pragma unroll
        for (int k16 = 0; k16 < 2; ++k16) {
            const int kc = k16 * 16;
            // B fragments: 32 n-cols = 2 ldm_x4
            uint32_t bh[4][2];
#pragma unroll
            for (int pr = 0; pr < 2; ++pr) {
                uint32_t addr = st + 2 * GS_ATILE * 2 +
                                ((wn * 32 + pr * 16 + brow) * HS + kc + bcol) * 2;
                uint32_t t4[4];
                ldm_x4(t4, addr);
                bh[2 * pr][0] = t4[0]; bh[2 * pr][1] = t4[1];
                bh[2 * pr + 1][0] = t4[2]; bh[2 * pr + 1][1] = t4[3];
            }
            // A streamed per mt (2 m-tiles of 16 rows)
#pragma unroll
            for (int mt = 0; mt < 2; ++mt) {
                uint32_t ah[4], al[4];
                uint32_t addr = st + ((wm * 32 + mt * 16 + arow) * HS + kc + acol) * 2;
                ldm_x4(ah, addr);
                ldm_x4(al, addr + GS_ATILE * 2);
#pragma unroll
                for (int nt = 0; nt < 4; ++nt) mma16816h(acc[mt][nt], ah, bh[nt]);
#pragma unroll
                for (int nt = 0; nt < 4; ++nt) mma16816h(acc[mt][nt], al, bh[nt]);
            }
        }
        __syncthreads();
    }

    if (MODE == 0) {
#pragma unroll
        for (int mt = 0; mt < 2; ++mt) {
            const int row = m0 + wm * 32 + mt * 16 + gid;
#pragma unroll
            for (int nt = 0; nt < 4; ++nt) {
                const int col = n0 + wn * 32 + nt * 8 + 2 * tig;
                *(float2*)(C + (size_t)row * Ntot + col)       = make_float2(acc[mt][nt][0], acc[mt][nt][1]);
                *(float2*)(C + (size_t)(row + 8) * Ntot + col) = make_float2(acc[mt][nt][2], acc[mt][nt][3]);
            }
        }
    } else {
        // fused rope + fp16 emit: stage fp32 tile (128 x 64) in dead pipeline smem
        float* stile = (float*)smem_raw;   // 128 x ESTR floats = 36864 B <= 51200
#pragma unroll
        for (int mt = 0; mt < 2; ++mt) {
            const int rl = wm * 32 + mt * 16 + gid;
#pragma unroll
            for (int nt = 0; nt < 4; ++nt) {
                const int cl = wn * 32 + nt * 8 + 2 * tig;
                stile[rl * ESTR + cl]           = acc[mt][nt][0];
                stile[rl * ESTR + cl + 1]       = acc[mt][nt][1];
                stile[(rl + 8) * ESTR + cl]     = acc[mt][nt][2];
                stile[(rl + 8) * ESTR + cl + 1] = acc[mt][nt][3];
            }
        }
        __syncthreads();

        // tile = exactly one 64-col head; rope pairs d <-> d+32 are in-tile
        const bool isV = (n0 >= 2560);
        const bool isQ = (n0 < 2048);
        // 128 rows x 16 even-d pairs = 2048 items
#pragma unroll 4
        for (int i = tid; i < 2048; i += 256) {
            int d = (i & 15) * 2;
            int r = i >> 4;
            int base = r * ESTR + d;
            float v1a = stile[base],      v1b = stile[base + 1];
            float v2a = stile[base + 32], v2b = stile[base + 33];
            int grow = m0 + r;
            int sidx = grow & (SEQ - 1);
            float y1a = v1a, y1b = v1b, y2a = v2a, y2b = v2b;
            if (!isV) {
                const float* cp = cosT + sidx * 64 + d;
                const float* sp = sinT + sidx * 64 + d;
                y1a = v1a * cp[0]  - v2a * sp[0];
                y1b = v1b * cp[1]  - v2b * sp[1];
                y2a = v2a * cp[32] + v1a * sp[32];
                y2b = v2b * cp[33] + v1b * sp[33];
            }
            if (isQ) {
                h16* o = Qh + (size_t)grow * DOUT + n0 + d;
                *(__half2*)o        = __floats2half2_rn(y1a * CS, y1b * CS);
                *(__half2*)(o + 32) = __floats2half2_rn(y2a * CS, y2b * CS);
            } else {
                h16* o = KVh + (size_t)grow * 1024 + (n0 - 2048) + d;
                *(__half2*)o        = __floats2half2_rn(y1a, y1b);
                *(__half2*)(o + 32) = __floats2half2_rn(y2a, y2b);
            }
        }
    }
}

// ---------------- fp16 tensor-core causal flash attention ------------------
#define STRH 72
#define ATT_QH  (128 * STRH)
#define ATT_KH  (128 * STRH)
#define ATT_VH  (128 * STRH)
#define ATT_SMEM ((ATT_QH + 2 * ATT_KH + 2 * ATT_VH) * 2)   // 92160 B

__device__ __forceinline__ void attn_load_kv16(const h16* __restrict__ KVh,
                                               uint32_t k_s, uint32_t v_s,
                                               int b, int g, int kb, int tid) {
#pragma unroll
    for (int t = 0; t < 8; ++t) {
        int idx = t * 256 + tid;
        int r = idx >> 4, c = idx & 15;
        const h16* row = KVh + (size_t)(b * SEQ + kb + r) * 1024 + g * HD;
        if (c < 8) cp16(k_s + (r * STRH + c * 8) * 2, row + c * 8);
        else       cp16(v_s + (r * STRH + (c - 8) * 8) * 2, row + 512 + (c - 8) * 8);
    }
    cp_commit();
}

__global__ __launch_bounds__(256, 2) void attn_fp16(const h16* __restrict__ Qh,
                                                    const h16* __restrict__ KVh,
                                                    h16* __restrict__ CTXh,
                                                    h16* __restrict__ CTXl) {
    extern __shared__ h16 smh[];
    h16* sQ = smh;
    h16* sK = smh + ATT_QH;
    h16* sV = smh + ATT_QH + 2 * ATT_KH;

    const int tid = threadIdx.x;
    const int lane = tid & 31;
    const int w = tid >> 5;
    const int gid = lane >> 2;
    const int tig = lane & 3;
    const int qt = (int)gridDim.x - 1 - (int)blockIdx.x;
    const int h = blockIdx.y;
    const int b = blockIdx.z;
    const int g = h >> 2;

    const uint32_t q_s = smem_u32(sQ);
    const uint32_t k_s = smem_u32(sK);
    const uint32_t v_s = smem_u32(sV);

#pragma unroll
    for (int t = 0; t < 4; ++t) {
        int idx = t * 256 + tid;
        int r = idx >> 3, c = idx & 7;
        cp16(q_s + (r * STRH + c * 8) * 2,
             Qh + (size_t)(b * SEQ + qt * 128 + r) * DOUT + h * HD + c * 8);
    }
    cp_commit();

    const int arow = lane & 15;
    const int acol = (lane >> 4) * 8;
    const int brow = (lane & 7) + ((lane >> 4) << 3);
    const int bcol = ((lane >> 3) & 1) * 8;
    const int vt_t = lane & 7;
    const int vt_q = lane >> 3;
    const int vrow = (vt_q & 1) * 8 + vt_t;
    const int vcol = (vt_q >> 1) * 8;

    cp_wait<0>();
    __syncthreads();

    uint32_t qf[4][4];
#pragma unroll
    for (int ks = 0; ks < 4; ++ks)
        ldm_x4(qf[ks], q_s + ((w * 16 + arow) * STRH + ks * 16 + acol) * 2);

    const int q0 = qt * 128 + w * 16;
    float m0 = -1e30f, m1 = -1e30f, l0 = 0.f, l1 = 0.f;
    float oa[8][4];
#pragma unroll
    for (int j = 0; j < 8; ++j)
#pragma unroll
        for (int r = 0; r < 4; ++r) oa[j][r] = 0.f;

    const int T = qt + 1;
    attn_load_kv16(KVh, k_s, v_s, b, g, 0, tid);

    for (int t = 0; t < T; ++t) {
        const int s = t & 1;
        if (t + 1 < T) {
            attn_load_kv16(KVh, k_s + (s ^ 1) * ATT_KH * 2,
                           v_s + (s ^ 1) * ATT_VH * 2, b, g, (t + 1) * 128, tid);
            cp_wait<1>();
        } else {
            cp_wait<0>();
        }
        __syncthreads();

        for (int half = 0; half < 2; ++half) {
            const int kb = t * 128 + half * 64;
            if (kb > q0 + 15) break;
            const uint32_t kcs = k_s + s * ATT_KH * 2 + half * 64 * STRH * 2;
            const uint32_t vcs = v_s + s * ATT_VH * 2 + half * 64 * STRH * 2;

            float sc[8][4];
#pragma unroll
            for (int j = 0; j < 8; ++j)
#pragma unroll
                for (int r = 0; r < 4; ++r) sc[j][r] = 0.f;

#pragma unroll
            for (int ks = 0; ks < 4; ++ks) {
                uint32_t kf[8][2];
#pragma unroll
                for (int kt = 0; kt < 4; ++kt) {
                    uint32_t t4[4];
                    ldm_x4(t4, kcs + ((kt * 16 + brow) * STRH + ks * 16 + bcol) * 2);
                    kf[2 * kt][0] = t4[0]; kf[2 * kt][1] = t4[1];
                    kf[2 * kt + 1][0] = t4[2]; kf[2 * kt + 1][1] = t4[3];
                }
#pragma unroll
                for (int jn = 0; jn < 8; ++jn)
                    mma16816h(sc[jn], qf[ks], kf[jn]);
            }

            if (kb + 63 > q0) {
                const int r0g = q0 + gid, r1g = r0g + 8;
#pragma unroll
                for (int jn = 0; jn < 8; ++jn) {
                    int col = kb + jn * 8 + 2 * tig;
                    if (col     > r0g) sc[jn][0] = -1e30f;
                    if (col + 1 > r0g) sc[jn][1] = -1e30f;
                    if (col     > r1g) sc[jn][2] = -1e30f;
                    if (col + 1 > r1g) sc[jn][3] = -1e30f;
                }
            }

            float rm0 = -1e30f, rm1 = -1e30f;
#pragma unroll
            for (int jn = 0; jn < 8; ++jn) {
                rm0 = fmaxf(rm0, fmaxf(sc[jn][0], sc[jn][1]));
                rm1 = fmaxf(rm1, fmaxf(sc[jn][2], sc[jn][3]));
            }
            rm0 = fmaxf(rm0, __shfl_xor_sync(0xffffffffu, rm0, 1));
            rm0 = fmaxf(rm0, __shfl_xor_sync(0xffffffffu, rm0, 2));
            rm1 = fmaxf(rm1, __shfl_xor_sync(0xffffffffu, rm1, 1));
            rm1 = fmaxf(rm1, __shfl_xor_sync(0xffffffffu, rm1, 2));

            float mn0 = fmaxf(m0, rm0), mn1 = fmaxf(m1, rm1);
            float c0 = ex2(m0 - mn0), c1 = ex2(m1 - mn1);
            m0 = mn0; m1 = mn1;

            float rs0 = 0.f, rs1 = 0.f;
#pragma unroll
            for (int jn = 0; jn < 8; ++jn) {
                sc[jn][0] = ex2(sc[jn][0] - m0);
                sc[jn][1] = ex2(sc[jn][1] - m0);
                sc[jn][2] = ex2(sc[jn][2] - m1);
                sc[jn][3] = ex2(sc[jn][3] - m1);
                rs0 += sc[jn][0] + sc[jn][1];
                rs1 += sc[jn][2] + sc[jn][3];
            }
            rs0 += __shfl_xor_sync(0xffffffffu, rs0, 1);
            rs0 += __shfl_xor_sync(0xffffffffu, rs0, 2);
            rs1 += __shfl_xor_sync(0xffffffffu, rs1, 1);
            rs1 += __shfl_xor_sync(0xffffffffu, rs1, 2);
            l0 = l0 * c0 + rs0;
            l1 = l1 * c1 + rs1;
#pragma unroll
            for (int jn = 0; jn < 8; ++jn) {
                oa[jn][0] *= c0; oa[jn][1] *= c0;
                oa[jn][2] *= c1; oa[jn][3] *= c1;
            }

#pragma unroll
            for (int j = 0; j < 4; ++j) {
                uint32_t pa[4];
                pa[0] = pack_h2(sc[2 * j][0],     sc[2 * j][1]);
                pa[1] = pack_h2(sc[2 * j][2],     sc[2 * j][3]);
                pa[2] = pack_h2(sc[2 * j + 1][0], sc[2 * j + 1][1]);
                pa[3] = pack_h2(sc[2 * j + 1][2], sc[2 * j + 1][3]);

                uint32_t vf[8][2];
#pragma unroll
                for (int vc = 0; vc < 4; ++vc) {
                    uint32_t t4[4];
                    ldm_x4t(t4, vcs + ((j * 16 + vrow) * STRH + vc * 16 + vcol) * 2);
                    vf[2 * vc][0] = t4[0]; vf[2 * vc][1] = t4[1];
                    vf[2 * vc + 1][0] = t4[2]; vf[2 * vc + 1][1] = t4[3];
                }
#pragma unroll
                for (int jn = 0; jn < 8; ++jn)
                    mma16816h(oa[jn], pa, vf[jn]);
            }
        }
        __syncthreads();
    }

    // epilogue: write CTX as fp16 hi/lo
    const float i0 = 1.f / l0, i1 = 1.f / l1;
    const size_t r0 = (size_t)(b * SEQ + q0 + gid) * DOUT + h * HD;
    const size_t r1 = (size_t)(b * SEQ + q0 + gid + 8) * DOUT + h * HD;
#pragma unroll
    for (int jn = 0; jn < 8; ++jn) {
        float v0 = oa[jn][0] * i0, v1 = oa[jn][1] * i0;
        float v2 = oa[jn][2] * i1, v3 = oa[jn][3] * i1;
        h16 h0, h1, h2, h3, lo0, lo1, lo2, lo3;
        split_h(v0, h0, lo0); split_h(v1, h1, lo1);
        split_h(v2, h2, lo2); split_h(v3, h3, lo3);
        size_t o0 = r0 + jn * 8 + 2 * tig;
        size_t o1 = r1 + jn * 8 + 2 * tig;
        *(__half2*)(CTXh + o0) = __halves2half2(h0, h1);
        *(__half2*)(CTXl + o0) = __halves2half2(lo0, lo1);
        *(__half2*)(CTXh + o1) = __halves2half2(h2, h3);
        *(__half2*)(CTXl + o1) = __halves2half2(lo2, lo3);
    }
}

// ---------------- kernel_launch ----------------
extern "C" void kernel_launch(void* const* d_in, const int* in_sizes, int n_in,
                              void* d_out, int out_size) {
    const float* x    = (const float*)d_in[0];
    const float* cosT = (const float*)d_in[1];
    const float* sinT = (const float*)d_in[2];
    const float* Wq   = (const float*)d_in[4];
    const float* Wk   = (const float*)d_in[5];
    const float* Wv   = (const float*)d_in[6];
    const float* Wo   = (const float*)d_in[7];
    float* out = (float*)d_out;

    h16 *Qh, *KVh, *Xh, *Xl, *CTXh, *CTXl, *WTh, *WoTh;
    cudaGetSymbolAddress((void**)&Qh,    g_Qh);
    cudaGetSymbolAddress((void**)&KVh,   g_KVh);
    cudaGetSymbolAddress((void**)&Xh,    g_Xh);
    cudaGetSymbolAddress((void**)&Xl,    g_Xl);
    cudaGetSymbolAddress((void**)&CTXh,  g_CTXh);
    cudaGetSymbolAddress((void**)&CTXl,  g_CTXl);
    cudaGetSymbolAddress((void**)&WTh,   g_WTh);
    cudaGetSymbolAddress((void**)&WoTh,  g_WoTh);

    cudaFuncSetAttribute(gemm_fp16x2<0>, cudaFuncAttributeMaxDynamicSharedMemorySize, GEMM_SMEM);
    cudaFuncSetAttribute(gemm_fp16x2<1>, cudaFuncAttributeMaxDynamicSharedMemorySize, GEMM_SMEM);
    cudaFuncSetAttribute(attn_fp16,      cudaFuncAttributeMaxDynamicSharedMemorySize, ATT_SMEM);

    // split x into fp16 hi/lo
    split_f32<<<(ROWS * DIN / 4 + 255) / 256, 256>>>(x, Xh, Xl, ROWS * DIN / 4);

    // one fused transpose launch for all weights (single fp16)
    transpose_all<<<dim3(160, 64), dim3(32, 8)>>>(Wq, Wk, Wv, Wo, WTh, WoTh);

    // fused QKV projection + rope + fp16 emit
    gemm_fp16x2<1><<<dim3(NQKV / BN, ROWS / BM), 256, GEMM_SMEM>>>(
        Xh, Xl, WTh, nullptr, NQKV, cosT, sinT, Qh, KVh);

    // fp16 tensor-core flash attention (128-key tiles)
    attn_fp16<<<dim3(SEQ / 128, NH, BATCH), 256, ATT_SMEM>>>(Qh, KVh, CTXh, CTXl);

    // output projection
    gemm_fp16x2<0><<<dim3(DOUT / BN, ROWS / BM), 256, GEMM_SMEM>>>(
        CTXh, CTXl, WoTh, out, DOUT, nullptr, nullptr, nullptr, nullptr);
}

// round 17
// speedup vs baseline: 1.1340x; 1.1340x over previous
#include <cuda_runtime.h>
#include <cuda_bf16.h>
#include <cuda_fp16.h>
#include <math.h>
#include <stdint.h>

// ---------------- problem constants ----------------
#define BATCH 2
#define SEQ   2048
#define DIN   2048
#define DOUT  2048
#define NH    32
#define HD    64
#define NKV   8
#define ROWS  4096          // BATCH*SEQ
#define NQKV  3072          // Q(2048) | K(512) | V(512) per row

typedef __half h16;

// ---------------- scratch (device globals; no runtime alloc) ----------------
__device__ h16 g_Qh [(size_t)ROWS * DOUT];     // rope'd, pre-scaled fp16 Q
__device__ h16 g_KVh[(size_t)ROWS * 1024];     // K(rope'd) | V fp16
__device__ h16 g_Xh [(size_t)ROWS * DIN];      // x fp16 hi
__device__ h16 g_Xl [(size_t)ROWS * DIN];      // x fp16 lo
__device__ h16 g_CTXh[(size_t)ROWS * DOUT];
__device__ h16 g_CTXl[(size_t)ROWS * DOUT];
__device__ h16 g_WTh[(size_t)NQKV * DIN];      // rows: Wq^T | Wk^T | Wv^T (fp16)
__device__ h16 g_WoTh[(size_t)DOUT * DIN];     // Wo^T (fp16)

// ---------------- helpers ----------------
__device__ __forceinline__ uint32_t smem_u32(const void* p) {
    uint32_t a;
    asm("{ .reg .u64 t; cvta.to.shared.u64 t, %1; cvt.u32.u64 %0, t; }" : "=r"(a) : "l"(p));
    return a;
}
__device__ __forceinline__ void cp16(uint32_t dst, const void* src) {
    asm volatile("cp.async.cg.shared.global [%0], [%1], 16;" :: "r"(dst), "l"(src) : "memory");
}
__device__ __forceinline__ void cp_commit() { asm volatile("cp.async.commit_group;" ::: "memory"); }
template<int N> __device__ __forceinline__ void cp_wait() {
    asm volatile("cp.async.wait_group %0;" :: "n"(N) : "memory");
}
__device__ __forceinline__ float ex2(float x) {
    float y; asm("ex2.approx.ftz.f32 %0, %1;" : "=f"(y) : "f"(x)); return y;
}
__device__ __forceinline__ void mma16816h(float* d, const uint32_t* a, const uint32_t* b) {
    asm volatile("mma.sync.aligned.m16n8k16.row.col.f32.f16.f16.f32 "
        "{%0,%1,%2,%3}, {%4,%5,%6,%7}, {%8,%9}, {%0,%1,%2,%3};"
        : "+f"(d[0]), "+f"(d[1]), "+f"(d[2]), "+f"(d[3])
        : "r"(a[0]), "r"(a[1]), "r"(a[2]), "r"(a[3]), "r"(b[0]), "r"(b[1]));
}
__device__ __forceinline__ void ldm_x4(uint32_t* r, uint32_t addr) {
    asm volatile("ldmatrix.sync.aligned.m8n8.x4.shared.b16 {%0,%1,%2,%3}, [%4];"
        : "=r"(r[0]), "=r"(r[1]), "=r"(r[2]), "=r"(r[3]) : "r"(addr));
}
__device__ __forceinline__ void ldm_x4t(uint32_t* r, uint32_t addr) {
    asm volatile("ldmatrix.sync.aligned.m8n8.x4.trans.shared.b16 {%0,%1,%2,%3}, [%4];"
        : "=r"(r[0]), "=r"(r[1]), "=r"(r[2]), "=r"(r[3]) : "r"(addr));
}
__device__ __forceinline__ void split_h(float v, h16& h, h16& l) {
    h = __float2half_rn(v);
    l = __float2half_rn(v - __half2float(h));
}
__device__ __forceinline__ uint32_t pack_h2(float lo, float hi) {
    __half2 h = __floats2half2_rn(lo, hi);
    return *(uint32_t*)&h;
}

// ---------------- split fp32 -> fp16 hi/lo ----------------
__global__ void split_f32(const float* __restrict__ in, h16* __restrict__ oh,
                          h16* __restrict__ ol, int n4) {
    int i = blockIdx.x * blockDim.x + threadIdx.x;
    if (i >= n4) return;
    float4 v = ((const float4*)in)[i];
    h16 h0, h1, h2, h3, l0, l1, l2, l3;
    split_h(v.x, h0, l0); split_h(v.y, h1, l1);
    split_h(v.z, h2, l2); split_h(v.w, h3, l3);
    ((__half2*)oh)[2 * i]     = __halves2half2(h0, h1);
    ((__half2*)oh)[2 * i + 1] = __halves2half2(h2, h3);
    ((__half2*)ol)[2 * i]     = __halves2half2(l0, l1);
    ((__half2*)ol)[2 * i + 1] = __halves2half2(l2, l3);
}

// ---------------- fused transpose (to fp16) for ALL weights -----------------
__global__ void transpose_all(const float* __restrict__ Wq, const float* __restrict__ Wk,
                              const float* __restrict__ Wv, const float* __restrict__ Wo,
                              h16* __restrict__ WTh, h16* __restrict__ WoTh) {
    __shared__ float t[32][33];
    const int bx = blockIdx.x;
    const int kb = blockIdx.y * 32;
    const float* src; h16* dh; int N, nb;
    if (bx < 64)       { src = Wq; N = 2048; nb = bx * 32;        dh = WTh; }
    else if (bx < 80)  { src = Wk; N = 512;  nb = (bx - 64) * 32; dh = WTh + (size_t)2048 * DIN; }
    else if (bx < 96)  { src = Wv; N = 512;  nb = (bx - 80) * 32; dh = WTh + (size_t)2560 * DIN; }
    else               { src = Wo; N = 2048; nb = (bx - 96) * 32; dh = WoTh; }

    int tx = threadIdx.x, ty = threadIdx.y; // 32 x 8
#pragma unroll
    for (int i = 0; i < 32; i += 8)
        t[ty + i][tx] = src[(size_t)(kb + ty + i) * N + nb + tx];
    __syncthreads();
#pragma unroll
    for (int i = 0; i < 32; i += 8)
        dh[(size_t)(nb + ty + i) * DIN + kb + tx] = __float2half_rn(t[tx][ty + i]);
}

// ---------------- fp16 2-term mma.sync GEMM: C = (Ah+Al)*Bh^T ---------------
// CTA 128x128, BK=64 (32 k-iterations), 2-stage cp.async, 2 CTAs/SM.
// MODE 0: plain fp32 C output. MODE 1: fused rope + fp16 emit to Qh/KVh.
#define BM 128
#define BN 128
#define BK 64
#define NSTG 2
#define KITER (DIN / BK)                   // 32
#define HS 72                              // halfs per smem row (144B stride)
#define GS_TILE (128 * HS)                 // halfs per matrix tile (9216)
#define GS_STAGE (3 * GS_TILE)             // Ah, Al, Bh
#define GEMM_SMEM (NSTG * GS_STAGE * 2)    // 110592 B
#define CS 0.1803368801111244f             // 0.125 / ln(2)
#define ESTR 136                           // fp32 staging stride (floats)

__device__ __forceinline__ void load_stage2(const h16* __restrict__ Ah,
                                            const h16* __restrict__ Al,
                                            const h16* __restrict__ Bh,
                                            uint32_t st, int m0, int n0, int k0, int tid) {
#pragma unroll
    for (int t = 0; t < 4; ++t) {
        int idx = t * 256 + tid;           // 0..1023: 128 rows x 8 chunks (8 halfs)
        int r = idx >> 3, c = idx & 7;
        uint32_t off = (r * HS + c * 8) * 2;
        size_t ga = (size_t)(m0 + r) * DIN + k0 + c * 8;
        size_t gb = (size_t)(n0 + r) * DIN + k0 + c * 8;
        cp16(st + off,                   Ah + ga);
        cp16(st + GS_TILE * 2 + off,     Al + ga);
        cp16(st + 2 * GS_TILE * 2 + off, Bh + gb);
    }
    cp_commit();
}

template<int MODE>
__global__ __launch_bounds__(256, 2) void gemm_fp16x2(const h16* __restrict__ Ah,
                                                      const h16* __restrict__ Al,
                                                      const h16* __restrict__ Bh,
                                                      float* __restrict__ C, int Ntot,
                                                      const float* __restrict__ cosT,
                                                      const float* __restrict__ sinT,
                                                      h16* __restrict__ Qh,
                                                      h16* __restrict__ KVh) {
    extern __shared__ char smem_raw[];
    const uint32_t sbase = smem_u32(smem_raw);
    const int tid  = threadIdx.x;
    const int lane = tid & 31;
    const int warp = tid >> 5;
    const int wm = warp & 1;
    const int wn = warp >> 1;
    const int gid = lane >> 2;
    const int tig = lane & 3;
    const int m0 = blockIdx.y * BM;
    const int n0 = blockIdx.x * BN;

    const int arow = lane & 15;
    const int acol = (lane >> 4) * 8;
    const int brow = (lane & 7) + ((lane >> 4) << 3);
    const int bcol = ((lane >> 3) & 1) * 8;

    float acc[4][4][4];
#pragma unroll
    for (int i = 0; i < 4; ++i)
#pragma unroll
        for (int j = 0; j < 4; ++j)
#pragma unroll
            for (int r = 0; r < 4; ++r) acc[i][j][r] = 0.f;

    load_stage2(Ah, Al, Bh, sbase, m0, n0, 0, tid);
    int load_it = 1;

    for (int it = 0; it < KITER; ++it) {
        bool issued = (load_it < KITER);
        if (issued) {
            load_stage2(Ah, Al, Bh, sbase + (load_it & 1) * GS_STAGE * 2,
                        m0, n0, load_it * BK, tid);
            ++load_it;
        }
        if (issued) cp_wait<1>(); else cp_wait<0>();
        __syncthreads();

        const uint32_t st = sbase + (it & 1) * GS_STAGE * 2;

#pragma unroll
        for (int k16 = 0; k16 < 4; ++k16) {
            const int kc = k16 * 16;
            // B fragments first (8 regs), then stream A per-mt (R14 pattern)
            uint32_t bh[4][2];
#pragma unroll
            for (int pr = 0; pr < 2; ++pr) {
                uint32_t addr = st + 2 * GS_TILE * 2 +
                                ((wn * 32 + pr * 16 + brow) * HS + kc + bcol) * 2;
                uint32_t t4[4];
                ldm_x4(t4, addr);
                bh[2 * pr][0] = t4[0]; bh[2 * pr][1] = t4[1];
                bh[2 * pr + 1][0] = t4[2]; bh[2 * pr + 1][1] = t4[3];
            }
#pragma unroll
            for (int mt = 0; mt < 4; ++mt) {
                uint32_t ah[4], al[4];
                uint32_t addr = st + ((wm * 64 + mt * 16 + arow) * HS + kc + acol) * 2;
                ldm_x4(ah, addr);
                ldm_x4(al, addr + GS_TILE * 2);
#pragma unroll
                for (int nt = 0; nt < 4; ++nt) {
                    mma16816h(acc[mt][nt], ah, bh[nt]);
                    mma16816h(acc[mt][nt], al, bh[nt]);
                }
            }
        }
        __syncthreads();
    }

    if (MODE == 0) {
#pragma unroll
        for (int mt = 0; mt < 4; ++mt) {
            const int row = m0 + wm * 64 + mt * 16 + gid;
#pragma unroll
            for (int nt = 0; nt < 4; ++nt) {
                const int col = n0 + wn * 32 + nt * 8 + 2 * tig;
                *(float2*)(C + (size_t)row * Ntot + col)       = make_float2(acc[mt][nt][0], acc[mt][nt][1]);
                *(float2*)(C + (size_t)(row + 8) * Ntot + col) = make_float2(acc[mt][nt][2], acc[mt][nt][3]);
            }
        }
    } else {
        // fused rope + fp16 emit: stage fp32 tile in (now dead) pipeline smem
        float* stile = (float*)smem_raw;   // 128 x ESTR floats = 69632 B <= 110592
#pragma unroll
        for (int mt = 0; mt < 4; ++mt) {
            const int rl = wm * 64 + mt * 16 + gid;
#pragma unroll
            for (int nt = 0; nt < 4; ++nt) {
                const int cl = wn * 32 + nt * 8 + 2 * tig;
                stile[rl * ESTR + cl]           = acc[mt][nt][0];
                stile[rl * ESTR + cl + 1]       = acc[mt][nt][1];
                stile[(rl + 8) * ESTR + cl]     = acc[mt][nt][2];
                stile[(rl + 8) * ESTR + cl + 1] = acc[mt][nt][3];
            }
        }
        __syncthreads();

        const bool isV = (n0 >= 2560);
        const bool isQ = (n0 < 2048);
#pragma unroll 4
        for (int i = tid; i < 4096; i += 256) {
            int d    = (i & 15) * 2;
            int head = (i >> 4) & 1;
            int r    = i >> 5;
            int base = r * ESTR + head * 64 + d;
            float v1a = stile[base],      v1b = stile[base + 1];
            float v2a = stile[base + 32], v2b = stile[base + 33];
            int grow = m0 + r;
            int sidx = grow & (SEQ - 1);
            float y1a = v1a, y1b = v1b, y2a = v2a, y2b = v2b;
            if (!isV) {
                const float* cp = cosT + sidx * 64 + d;
                const float* sp = sinT + sidx * 64 + d;
                y1a = v1a * cp[0]  - v2a * sp[0];
                y1b = v1b * cp[1]  - v2b * sp[1];
                y2a = v2a * cp[32] + v1a * sp[32];
                y2b = v2b * cp[33] + v1b * sp[33];
            }
            if (isQ) {
                h16* o = Qh + (size_t)grow * DOUT + n0 + head * 64 + d;
                *(__half2*)o        = __floats2half2_rn(y1a * CS, y1b * CS);
                *(__half2*)(o + 32) = __floats2half2_rn(y2a * CS, y2b * CS);
            } else {
                h16* o = KVh + (size_t)grow * 1024 + (n0 - 2048) + head * 64 + d;
                *(__half2*)o        = __floats2half2_rn(y1a, y1b);
                *(__half2*)(o + 32) = __floats2half2_rn(y2a, y2b);
            }
        }
    }
}

// ---------------- fp16 tensor-core causal flash attention ------------------
#define STRH 72
#define ATT_QH  (128 * STRH)
#define ATT_KH  (128 * STRH)
#define ATT_VH  (128 * STRH)
#define ATT_SMEM ((ATT_QH + 2 * ATT_KH + 2 * ATT_VH) * 2)   // 92160 B

__device__ __forceinline__ void attn_load_kv16(const h16* __restrict__ KVh,
                                               uint32_t k_s, uint32_t v_s,
                                               int b, int g, int kb, int tid) {
#pragma unroll
    for (int t = 0; t < 8; ++t) {
        int idx = t * 256 + tid;
        int r = idx >> 4, c = idx & 15;
        const h16* row = KVh + (size_t)(b * SEQ + kb + r) * 1024 + g * HD;
        if (c < 8) cp16(k_s + (r * STRH + c * 8) * 2, row + c * 8);
        else       cp16(v_s + (r * STRH + (c - 8) * 8) * 2, row + 512 + (c - 8) * 8);
    }
    cp_commit();
}

__global__ __launch_bounds__(256, 2) void attn_fp16(const h16* __restrict__ Qh,
                                                    const h16* __restrict__ KVh,
                                                    h16* __restrict__ CTXh,
                                                    h16* __restrict__ CTXl) {
    extern __shared__ h16 smh[];
    h16* sQ = smh;
    h16* sK = smh + ATT_QH;
    h16* sV = smh + ATT_QH + 2 * ATT_KH;

    const int tid = threadIdx.x;
    const int lane = tid & 31;
    const int w = tid >> 5;
    const int gid = lane >> 2;
    const int tig = lane & 3;
    const int qt = (int)gridDim.x - 1 - (int)blockIdx.x;
    const int h = blockIdx.y;
    const int b = blockIdx.z;
    const int g = h >> 2;

    const uint32_t q_s = smem_u32(sQ);
    const uint32_t k_s = smem_u32(sK);
    const uint32_t v_s = smem_u32(sV);

#pragma unroll
    for (int t = 0; t < 4; ++t) {
        int idx = t * 256 + tid;
        int r = idx >> 3, c = idx & 7;
        cp16(q_s + (r * STRH + c * 8) * 2,
             Qh + (size_t)(b * SEQ + qt * 128 + r) * DOUT + h * HD + c * 8);
    }
    cp_commit();

    const int arow = lane & 15;
    const int acol = (lane >> 4) * 8;
    const int brow = (lane & 7) + ((lane >> 4) << 3);
    const int bcol = ((lane >> 3) & 1) * 8;
    const int vt_t = lane & 7;
    const int vt_q = lane >> 3;
    const int vrow = (vt_q & 1) * 8 + vt_t;
    const int vcol = (vt_q >> 1) * 8;

    cp_wait<0>();
    __syncthreads();

    uint32_t qf[4][4];
#pragma unroll
    for (int ks = 0; ks < 4; ++ks)
        ldm_x4(qf[ks], q_s + ((w * 16 + arow) * STRH + ks * 16 + acol) * 2);

    const int q0 = qt * 128 + w * 16;
    float m0 = -1e30f, m1 = -1e30f, l0 = 0.f, l1 = 0.f;
    float oa[8][4];
#pragma unroll
    for (int j = 0; j < 8; ++j)
#pragma unroll
        for (int r = 0; r < 4; ++r) oa[j][r] = 0.f;

    const int T = qt + 1;
    attn_load_kv16(KVh, k_s, v_s, b, g, 0, tid);

    for (int t = 0; t < T; ++t) {
        const int s = t & 1;
        if (t + 1 < T) {
            attn_load_kv16(KVh, k_s + (s ^ 1) * ATT_KH * 2,
                           v_s + (s ^ 1) * ATT_VH * 2, b, g, (t + 1) * 128, tid);
            cp_wait<1>();
        } else {
            cp_wait<0>();
        }
        __syncthreads();

        for (int half = 0; half < 2; ++half) {
            const int kb = t * 128 + half * 64;
            if (kb > q0 + 15) break;
            const uint32_t kcs = k_s + s * ATT_KH * 2 + half * 64 * STRH * 2;
            const uint32_t vcs = v_s + s * ATT_VH * 2 + half * 64 * STRH * 2;

            float sc[8][4];
#pragma unroll
            for (int j = 0; j < 8; ++j)
#pragma unroll
                for (int r = 0; r < 4; ++r) sc[j][r] = 0.f;

#pragma unroll
            for (int ks = 0; ks < 4; ++ks) {
                uint32_t kf[8][2];
#pragma unroll
                for (int kt = 0; kt < 4; ++kt) {
                    uint32_t t4[4];
                    ldm_x4(t4, kcs + ((kt * 16 + brow) * STRH + ks * 16 + bcol) * 2);
                    kf[2 * kt][0] = t4[0]; kf[2 * kt][1] = t4[1];
                    kf[2 * kt + 1][0] = t4[2]; kf[2 * kt + 1][1] = t4[3];
                }
#pragma unroll
                for (int jn = 0; jn < 8; ++jn)
                    mma16816h(sc[jn], qf[ks], kf[jn]);
            }

            if (kb + 63 > q0) {
                const int r0g = q0 + gid, r1g = r0g + 8;
#pragma unroll
                for (int jn = 0; jn < 8; ++jn) {
                    int col = kb + jn * 8 + 2 * tig;
                    if (col     > r0g) sc[jn][0] = -1e30f;
                    if (col + 1 > r0g) sc[jn][1] = -1e30f;
                    if (col     > r1g) sc[jn][2] = -1e30f;
                    if (col + 1 > r1g) sc[jn][3] = -1e30f;
                }
            }

            float rm0 = -1e30f, rm1 = -1e30f;
#pragma unroll
            for (int jn = 0; jn < 8; ++jn) {
                rm0 = fmaxf(rm0, fmaxf(sc[jn][0], sc[jn][1]));
                rm1 = fmaxf(rm1, fmaxf(sc[jn][2], sc[jn][3]));
            }
            rm0 = fmaxf(rm0, __shfl_xor_sync(0xffffffffu, rm0, 1));
            rm0 = fmaxf(rm0, __shfl_xor_sync(0xffffffffu, rm0, 2));
            rm1 = fmaxf(rm1, __shfl_xor_sync(0xffffffffu, rm1, 1));
            rm1 = fmaxf(rm1, __shfl_xor_sync(0xffffffffu, rm1, 2));

            float mn0 = fmaxf(m0, rm0), mn1 = fmaxf(m1, rm1);
            float c0 = ex2(m0 - mn0), c1 = ex2(m1 - mn1);
            m0 = mn0; m1 = mn1;

            float rs0 = 0.f, rs1 = 0.f;
#pragma unroll
            for (int jn = 0; jn < 8; ++jn) {
                sc[jn][0] = ex2(sc[jn][0] - m0);
                sc[jn][1] = ex2(sc[jn][1] - m0);
                sc[jn][2] = ex2(sc[jn][2] - m1);
                sc[jn][3] = ex2(sc[jn][3] - m1);
                rs0 += sc[jn][0] + sc[jn][1];
                rs1 += sc[jn][2] + sc[jn][3];
            }
            rs0 += __shfl_xor_sync(0xffffffffu, rs0, 1);
            rs0 += __shfl_xor_sync(0xffffffffu, rs0, 2);
            rs1 += __shfl_xor_sync(0xffffffffu, rs1, 1);
            rs1 += __shfl_xor_sync(0xffffffffu, rs1, 2);
            l0 = l0 * c0 + rs0;
            l1 = l1 * c1 + rs1;
#pragma unroll
            for (int jn = 0; jn < 8; ++jn) {
                oa[jn][0] *= c0; oa[jn][1] *= c0;
                oa[jn][2] *= c1; oa[jn][3] *= c1;
            }

#pragma unroll
            for (int j = 0; j < 4; ++j) {
                uint32_t pa[4];
                pa[0] = pack_h2(sc[2 * j][0],     sc[2 * j][1]);
                pa[1] = pack_h2(sc[2 * j][2],     sc[2 * j][3]);
                pa[2] = pack_h2(sc[2 * j + 1][0], sc[2 * j + 1][1]);
                pa[3] = pack_h2(sc[2 * j + 1][2], sc[2 * j + 1][3]);

                uint32_t vf[8][2];
#pragma unroll
                for (int vc = 0; vc < 4; ++vc) {
                    uint32_t t4[4];
                    ldm_x4t(t4, vcs + ((j * 16 + vrow) * STRH + vc * 16 + vcol) * 2);
                    vf[2 * vc][0] = t4[0]; vf[2 * vc][1] = t4[1];
                    vf[2 * vc + 1][0] = t4[2]; vf[2 * vc + 1][1] = t4[3];
                }
#pragma unroll
                for (int jn = 0; jn < 8; ++jn)
                    mma16816h(oa[jn], pa, vf[jn]);
            }
        }
        __syncthreads();
    }

    // epilogue: write CTX as fp16 hi/lo
    const float i0 = 1.f / l0, i1 = 1.f / l1;
    const size_t r0 = (size_t)(b * SEQ + q0 + gid) * DOUT + h * HD;
    const size_t r1 = (size_t)(b * SEQ + q0 + gid + 8) * DOUT + h * HD;
#pragma unroll
    for (int jn = 0; jn < 8; ++jn) {
        float v0 = oa[jn][0] * i0, v1 = oa[jn][1] * i0;
        float v2 = oa[jn][2] * i1, v3 = oa[jn][3] * i1;
        h16 h0, h1, h2, h3, lo0, lo1, lo2, lo3;
        split_h(v0, h0, lo0); split_h(v1, h1, lo1);
        split_h(v2, h2, lo2); split_h(v3, h3, lo3);
        size_t o0 = r0 + jn * 8 + 2 * tig;
        size_t o1 = r1 + jn * 8 + 2 * tig;
        *(__half2*)(CTXh + o0) = __halves2half2(h0, h1);
        *(__half2*)(CTXl + o0) = __halves2half2(lo0, lo1);
        *(__half2*)(CTXh + o1) = __halves2half2(h2, h3);
        *(__half2*)(CTXl + o1) = __halves2half2(lo2, lo3);
    }
}

// ---------------- kernel_launch ----------------
extern "C" void kernel_launch(void* const* d_in, const int* in_sizes, int n_in,
                              void* d_out, int out_size) {
    const float* x    = (const float*)d_in[0];
    const float* cosT = (const float*)d_in[1];
    const float* sinT = (const float*)d_in[2];
    const float* Wq   = (const float*)d_in[4];
    const float* Wk   = (const float*)d_in[5];
    const float* Wv   = (const float*)d_in[6];
    const float* Wo   = (const float*)d_in[7];
    float* out = (float*)d_out;

    h16 *Qh, *KVh, *Xh, *Xl, *CTXh, *CTXl, *WTh, *WoTh;
    cudaGetSymbolAddress((void**)&Qh,    g_Qh);
    cudaGetSymbolAddress((void**)&KVh,   g_KVh);
    cudaGetSymbolAddress((void**)&Xh,    g_Xh);
    cudaGetSymbolAddress((void**)&Xl,    g_Xl);
    cudaGetSymbolAddress((void**)&CTXh,  g_CTXh);
    cudaGetSymbolAddress((void**)&CTXl,  g_CTXl);
    cudaGetSymbolAddress((void**)&WTh,   g_WTh);
    cudaGetSymbolAddress((void**)&WoTh,  g_WoTh);

    cudaFuncSetAttribute(gemm_fp16x2<0>, cudaFuncAttributeMaxDynamicSharedMemorySize, GEMM_SMEM);
    cudaFuncSetAttribute(gemm_fp16x2<1>, cudaFuncAttributeMaxDynamicSharedMemorySize, GEMM_SMEM);
    cudaFuncSetAttribute(attn_fp16,      cudaFuncAttributeMaxDynamicSharedMemorySize, ATT_SMEM);

    // split x into fp16 hi/lo
    split_f32<<<(ROWS * DIN / 4 + 255) / 256, 256>>>(x, Xh, Xl, ROWS * DIN / 4);

    // one fused transpose launch for all weights (single fp16)
    transpose_all<<<dim3(160, 64), dim3(32, 8)>>>(Wq, Wk, Wv, Wo, WTh, WoTh);

    // fused QKV projection + rope + fp16 emit
    gemm_fp16x2<1><<<dim3(NQKV / BN, ROWS / BM), 256, GEMM_SMEM>>>(
        Xh, Xl, WTh, nullptr, NQKV, cosT, sinT, Qh, KVh);

    // fp16 tensor-core flash attention (128-key tiles)
    attn_fp16<<<dim3(SEQ / 128, NH, BATCH), 256, ATT_SMEM>>>(Qh, KVh, CTXh, CTXl);

    // output projection
    gemm_fp16x2<0><<<dim3(DOUT / BN, ROWS / BM), 256, GEMM_SMEM>>>(
        CTXh, CTXl, WoTh, out, DOUT, nullptr, nullptr, nullptr, nullptr);
}